// round 15
// baseline (speedup 1.0000x reference)
#include <cuda_runtime.h>
#include <cuda_bf16.h>
#include <cuda_fp16.h>
#include <math.h>
#include <stdint.h>

#define SEQ    4096
#define DIM    1024
#define HEADS  16
#define DHEAD  64
#define KP     (3 * DIM)          // split-K': [hi|hi|lo] / [hi|lo|hi]
#define BK     32
#define SCLOG2 0.1803368801111204f   // (1/8) * log2(e)

// ---------------- scratch (__device__ globals; no allocs allowed) ----------
__device__ __nv_bfloat16 g_XS[SEQ * KP];
__device__ __nv_bfloat16 g_WTq[DIM * KP];
__device__ __nv_bfloat16 g_WTk[DIM * KP];
__device__ __nv_bfloat16 g_WTv[DIM * KP];
__device__ __nv_bfloat16 g_WTo[DIM * KP];
__device__ __half        g_Qh [SEQ * DIM];   // fp16, pre-scaled by SCLOG2
__device__ __half        g_Khi[SEQ * DIM];   // fp16 hi
__device__ __half        g_Klo[SEQ * DIM];   // fp16 lo
__device__ __half        g_Vh [SEQ * DIM];
__device__ __nv_bfloat16 g_OS[SEQ * KP];     // attention out, split layout

// ---------------- helpers (non-arch-specific PTX, sm_80+) ------------------
__device__ __forceinline__ uint32_t smem_u32(const void* p) {
    return (uint32_t)__cvta_generic_to_shared(p);
}
__device__ __forceinline__ void cp16(uint32_t dst, const void* src) {
    asm volatile("cp.async.cg.shared.global [%0], [%1], 16;"
                 :: "r"(dst), "l"(src) : "memory");
}
__device__ __forceinline__ void cp_commit() {
    asm volatile("cp.async.commit_group;" ::: "memory");
}
template <int N>
__device__ __forceinline__ void cp_wait() {
    asm volatile("cp.async.wait_group %0;" :: "n"(N) : "memory");
}
__device__ __forceinline__ void ldm_x4(uint32_t* r, uint32_t addr) {
    asm volatile("ldmatrix.sync.aligned.m8n8.x4.shared.b16 {%0,%1,%2,%3}, [%4];"
                 : "=r"(r[0]), "=r"(r[1]), "=r"(r[2]), "=r"(r[3]) : "r"(addr));
}
__device__ __forceinline__ void ldm_x4t(uint32_t* r, uint32_t addr) {
    asm volatile("ldmatrix.sync.aligned.m8n8.x4.trans.shared.b16 {%0,%1,%2,%3}, [%4];"
                 : "=r"(r[0]), "=r"(r[1]), "=r"(r[2]), "=r"(r[3]) : "r"(addr));
}
__device__ __forceinline__ void mma16816(float* c, const uint32_t* a,
                                         const uint32_t* b) {
    asm volatile("mma.sync.aligned.m16n8k16.row.col.f32.bf16.bf16.f32 "
                 "{%0,%1,%2,%3}, {%4,%5,%6,%7}, {%8,%9}, {%0,%1,%2,%3};"
                 : "+f"(c[0]), "+f"(c[1]), "+f"(c[2]), "+f"(c[3])
                 : "r"(a[0]), "r"(a[1]), "r"(a[2]), "r"(a[3]),
                   "r"(b[0]), "r"(b[1]));
}
__device__ __forceinline__ void mma16816h(float* c, const uint32_t* a,
                                          uint32_t b0, uint32_t b1) {
    asm volatile("mma.sync.aligned.m16n8k16.row.col.f32.f16.f16.f32 "
                 "{%0,%1,%2,%3}, {%4,%5,%6,%7}, {%8,%9}, {%0,%1,%2,%3};"
                 : "+f"(c[0]), "+f"(c[1]), "+f"(c[2]), "+f"(c[3])
                 : "r"(a[0]), "r"(a[1]), "r"(a[2]), "r"(a[3]),
                   "r"(b0), "r"(b1));
}
__device__ __forceinline__ uint32_t exp2_f16x2(float lo, float hi) {
    uint32_t hreg, p;
    asm volatile("cvt.rn.f16x2.f32 %0, %1, %2;" : "=r"(hreg) : "f"(hi), "f"(lo));
    asm volatile("ex2.approx.f16x2 %0, %1;" : "=r"(p) : "r"(hreg));
    return p;
}
__device__ __forceinline__ float ex2f(float x) {
    float y; asm volatile("ex2.approx.f32 %0, %1;" : "=f"(y) : "f"(x)); return y;
}
__device__ __forceinline__ void store_bf16x2(__nv_bfloat16* p, float a, float b) {
    __nv_bfloat162 v(__float2bfloat16(a), __float2bfloat16(b));
    *(__nv_bfloat162*)p = v;
}

// ---------------------------------------------------------------------------
// Split conversions (GEMM inputs)
// ---------------------------------------------------------------------------
__global__ void __launch_bounds__(256)
split_a_kernel(const float* __restrict__ X, __nv_bfloat16* __restrict__ XS, int K)
{
    int idx = (blockIdx.x * 256 + threadIdx.x) * 4;
    int m = idx / K, k = idx % K;
    float4 v = *(const float4*)(X + idx);
    __nv_bfloat16 h0 = __float2bfloat16(v.x), h1 = __float2bfloat16(v.y);
    __nv_bfloat16 h2 = __float2bfloat16(v.z), h3 = __float2bfloat16(v.w);
    __nv_bfloat16 l0 = __float2bfloat16(v.x - __bfloat162float(h0));
    __nv_bfloat16 l1 = __float2bfloat16(v.y - __bfloat162float(h1));
    __nv_bfloat16 l2 = __float2bfloat16(v.z - __bfloat162float(h2));
    __nv_bfloat16 l3 = __float2bfloat16(v.w - __bfloat162float(h3));
    __nv_bfloat162 hA = __nv_bfloat162(h0, h1), hB = __nv_bfloat162(h2, h3);
    __nv_bfloat162 lA = __nv_bfloat162(l0, l1), lB = __nv_bfloat162(l2, l3);
    __nv_bfloat162* base = (__nv_bfloat162*)(XS + (size_t)m * (3 * K) + k);
    base[0] = hA; base[1] = hB;
    base[K / 2] = hA; base[K / 2 + 1] = hB;
    base[K] = lA; base[K + 1] = lB;
}

__global__ void __launch_bounds__(256)
split_w_kernel(const float* __restrict__ W, __nv_bfloat16* __restrict__ WT, int K, int N)
{
    __shared__ float t[32][33];
    const int tx = threadIdx.x & 31, ty = threadIdx.x >> 5;
    const int k0 = blockIdx.y * 32, n0 = blockIdx.x * 32;
#pragma unroll
    for (int i = 0; i < 4; i++)
        t[ty + i * 8][tx] = W[(size_t)(k0 + ty + i * 8) * N + n0 + tx];
    __syncthreads();
#pragma unroll
    for (int i = 0; i < 4; i++) {
        float v = t[tx][ty + i * 8];
        __nv_bfloat16 h = __float2bfloat16(v);
        __nv_bfloat16 l = __float2bfloat16(v - __bfloat162float(h));
        int n = n0 + ty + i * 8;
        __nv_bfloat16* row = WT + (size_t)n * (3 * K);
        row[k0 + tx] = h;
        row[K + k0 + tx] = l;
        row[2 * K + k0 + tx] = h;
    }
}

// ---------------------------------------------------------------------------
// HMMA GEMM (TN). 128 threads, 4 warps (2x2), warp tile 64x64.
// MODE: 0 = Q (scale, fp16, 2-pass K'=2048), 1 = K (fp16 hi/lo, 2-pass),
// 2 = V (fp16, 3-pass), 3 = fp32 + bias (3-pass).
// ---------------------------------------------------------------------------
#define ROWB   80
#define TILEB  (128 * ROWB)

template <int MODE>
__global__ void __launch_bounds__(128, 2)
gemm_mma_kernel(const __nv_bfloat16* __restrict__ A,
                const __nv_bfloat16* __restrict__ Bt,
                const float* __restrict__ bias, float* __restrict__ C,
                __half* __restrict__ H0, __half* __restrict__ H1, int N)
{
    __shared__ __align__(128) char smem[4 * TILEB];
    const int NITER = (MODE <= 1) ? 64 : 96;   // 2-pass vs 3-pass K'

    const int tid  = threadIdx.x;
    const int lane = tid & 31, wid = tid >> 5;
    const int wm0  = (wid & 1) * 64;
    const int wn0  = (wid >> 1) * 64;
    const int m0 = blockIdx.y * 128, n0 = blockIdx.x * 128;

    const uint32_t sbase = smem_u32(smem);
    const uint32_t sA[2] = { sbase,             sbase + TILEB };
    const uint32_t sB[2] = { sbase + 2 * TILEB, sbase + 3 * TILEB };

    float acc[4][8][4];
#pragma unroll
    for (int i = 0; i < 4; i++)
#pragma unroll
        for (int j = 0; j < 8; j++)
#pragma unroll
            for (int r = 0; r < 4; r++) acc[i][j][r] = 0.f;

    const int lrow = tid >> 2, lc16 = tid & 3;   // 128 thr: 32 rows x 4 chunks
    auto load_tile = [&](int c, int b) {
        const int kc0 = c * BK;
#pragma unroll
        for (int i = 0; i < 4; i++) {
            int row = lrow + i * 32;
            uint32_t so = (uint32_t)(row * ROWB + lc16 * 16);
            cp16(sA[b] + so, A  + (size_t)(m0 + row) * KP + kc0 + lc16 * 8);
            cp16(sB[b] + so, Bt + (size_t)(n0 + row) * KP + kc0 + lc16 * 8);
        }
        cp_commit();
    };

    load_tile(0, 0);

    for (int c = 0; c < NITER; c++) {
        const int b = c & 1;
        if (c + 1 < NITER) { load_tile(c + 1, b ^ 1); cp_wait<1>(); }
        else               { cp_wait<0>(); }
        __syncthreads();

#pragma unroll
        for (int s = 0; s < 2; s++) {
            uint32_t af[4][4], bf[4][4];
#pragma unroll
            for (int i = 0; i < 4; i++) {
                uint32_t addr = sA[b] + (uint32_t)((wm0 + i * 16 + (lane & 15)) * ROWB
                               + s * 32 + (lane >> 4) * 16);
                ldm_x4(af[i], addr);
            }
#pragma unroll
            for (int j = 0; j < 4; j++) {
                int grp = lane >> 3;
                int row = wn0 + j * 16 + (grp >> 1) * 8 + (lane & 7);
                uint32_t addr = sB[b] + (uint32_t)(row * ROWB + s * 32 + (grp & 1) * 16);
                ldm_x4(bf[j], addr);
            }
#pragma unroll
            for (int i = 0; i < 4; i++)
#pragma unroll
                for (int jj = 0; jj < 8; jj++)
                    mma16816(acc[i][jj], af[i], &bf[jj >> 1][(jj & 1) * 2]);
        }
        __syncthreads();
    }

#pragma unroll
    for (int i = 0; i < 4; i++) {
        int row = m0 + wm0 + i * 16 + (lane >> 2);
#pragma unroll
        for (int jj = 0; jj < 8; jj++) {
            int col = n0 + wn0 + jj * 8 + (lane & 3) * 2;
            float v[4] = { acc[i][jj][0], acc[i][jj][1],
                           acc[i][jj][2], acc[i][jj][3] };
            if (MODE == 3) {
                float b0 = bias[col], b1 = bias[col + 1];
                *(float2*)&C[(size_t)row * N + col] =
                    make_float2(v[0] + b0, v[1] + b1);
                *(float2*)&C[(size_t)(row + 8) * N + col] =
                    make_float2(v[2] + b0, v[3] + b1);
            } else if (MODE == 0) {
                *(__half2*)&H0[(size_t)row * N + col] =
                    __floats2half2_rn(v[0] * SCLOG2, v[1] * SCLOG2);
                *(__half2*)&H0[(size_t)(row + 8) * N + col] =
                    __floats2half2_rn(v[2] * SCLOG2, v[3] * SCLOG2);
            } else if (MODE == 2) {
                *(__half2*)&H0[(size_t)row * N + col] =
                    __floats2half2_rn(v[0], v[1]);
                *(__half2*)&H0[(size_t)(row + 8) * N + col] =
                    __floats2half2_rn(v[2], v[3]);
            } else {            // MODE 1: fp16 hi/lo split
                float h_[4], l_[4];
#pragma unroll
                for (int r = 0; r < 4; r++) {
                    h_[r] = __half2float(__float2half(v[r]));
                    l_[r] = v[r] - h_[r];
                }
                *(__half2*)&H0[(size_t)row * N + col]       = __floats2half2_rn(h_[0], h_[1]);
                *(__half2*)&H0[(size_t)(row + 8) * N + col] = __floats2half2_rn(h_[2], h_[3]);
                *(__half2*)&H1[(size_t)row * N + col]       = __floats2half2_rn(l_[0], l_[1]);
                *(__half2*)&H1[(size_t)(row + 8) * N + col] = __floats2half2_rn(l_[2], l_[3]);
            }
        }
    }
}

// ---------------------------------------------------------------------------
// HMMA flash attention (causal). CTA = 256 q-rows, 8 warps, warp = m32
// (two m16 slabs sharing every K/V fragment). Q fp16 pre-scaled, K fp16
// hi/lo (2 passes), V fp16. cp.async double-buffered K/V stages.
// ---------------------------------------------------------------------------
#define QROWS    256
#define PADB     144
#define QBYTES   (QROWS * PADB)               // 36864
#define KTILEB   (64 * PADB)                  // 9216
#define STAGEB   (3 * KTILEB)                 // 27648
#define ATT_SMEM (QBYTES + 2 * STAGEB)        // 92160

__global__ void __launch_bounds__(256)
attn_mma_kernel(const __half* __restrict__ Qh_g,
                const __half* __restrict__ Khi_g,
                const __half* __restrict__ Klo_g,
                const __half* __restrict__ Vh_g,
                __nv_bfloat16* __restrict__ OS)
{
    extern __shared__ __align__(16) char sraw[];
    const uint32_t sbase = smem_u32(sraw);
    const uint32_t qhb = sbase;
    const uint32_t stg = sbase + QBYTES;

    const int h   = blockIdx.y;
    const int qb  = (int)gridDim.x - 1 - (int)blockIdx.x;
    const int tid = threadIdx.x, lane = tid & 31, wid = tid >> 5;
    const int q0  = qb * QROWS;
    const int nkb = qb * 4 + 4;

    // Issue Q loads: 2048 16B chunks
#pragma unroll
    for (int i = 0; i < 8; i++) {
        int idx = tid + i * 256;
        int row = idx >> 3, c16 = idx & 7;
        cp16(qhb + (uint32_t)(row * PADB + c16 * 16),
             Qh_g + (size_t)(q0 + row) * DIM + h * DHEAD + c16 * 8);
    }

    // K/V stage loader: 1536 chunks (Khi, Klo, Vh)
    auto load_kv = [&](int kb, int b) {
        const int j0 = kb * 64;
        const uint32_t sb = stg + (uint32_t)b * STAGEB;
#pragma unroll
        for (int i = 0; i < 6; i++) {
            int idx = tid + i * 256;
            int arr = idx >> 9, rem = idx & 511;
            int row = rem >> 3, c16 = rem & 7;
            size_t goff = (size_t)(j0 + row) * DIM + h * DHEAD + c16 * 8;
            const void* src = (arr == 0) ? (const void*)(Khi_g + goff)
                            : (arr == 1) ? (const void*)(Klo_g + goff)
                                         : (const void*)(Vh_g + goff);
            cp16(sb + (uint32_t)(arr * KTILEB + row * PADB + c16 * 16), src);
        }
        cp_commit();
    };

    load_kv(0, 0);
    cp_wait<0>();
    __syncthreads();

    // Hoist Q fragments for both m16 slabs
    uint32_t aH[2][4][4];
#pragma unroll
    for (int sub = 0; sub < 2; sub++) {
        const uint32_t aoff = (uint32_t)((wid * 32 + sub * 16 + (lane & 15)) * PADB
                              + (lane >> 4) * 16);
#pragma unroll
        for (int t = 0; t < 4; t++)
            ldm_x4(aH[sub][t], qhb + aoff + t * 32);
    }

    float o[2][8][4], lf[2][4];
    float m_[2][2];
#pragma unroll
    for (int sub = 0; sub < 2; sub++) {
#pragma unroll
        for (int g = 0; g < 8; g++)
#pragma unroll
            for (int r = 0; r < 4; r++) o[sub][g][r] = 0.f;
#pragma unroll
        for (int r = 0; r < 4; r++) lf[sub][r] = 0.f;
        m_[sub][0] = -1e30f; m_[sub][1] = -1e30f;
    }

    const int grp = lane >> 3;
    const uint32_t bRowOff = (uint32_t)(((grp >> 1) * 8 + (lane & 7)) * PADB + (grp & 1) * 16);
    const uint32_t vRowOff = (uint32_t)((((lane & 7) + 8 * (grp & 1))) * PADB + (lane >> 4) * 16);
    const int wrow0 = q0 + wid * 32;            // warp's first q-row

    for (int kb = 0; kb < nkb; kb++) {
        const int b = kb & 1;
        if (kb + 1 < nkb) { load_kv(kb + 1, b ^ 1); cp_wait<1>(); }
        else              { cp_wait<0>(); }
        __syncthreads();

        const int j0 = kb * 64;
        if (wrow0 + 31 >= j0) {                 // warp not fully masked
            const uint32_t khb = stg + (uint32_t)b * STAGEB;
            const uint32_t klb = khb + KTILEB;
            const uint32_t vhb = klb + KTILEB;
            const bool act0 = (wrow0 + 15 >= j0);   // slab 0 active

            float s[2][8][4];
#pragma unroll
            for (int sub = 0; sub < 2; sub++)
#pragma unroll
                for (int g = 0; g < 8; g++)
#pragma unroll
                    for (int r = 0; r < 4; r++) s[sub][g][r] = 0.f;

            // S = Q.Khi + Q.Klo — K fragments shared across both slabs
#pragma unroll
            for (int pass = 0; pass < 2; pass++) {
                const uint32_t bb = pass ? klb : khb;
#pragma unroll
                for (int t = 0; t < 4; t++) {
#pragma unroll
                    for (int g = 0; g < 4; g++) {
                        uint32_t bq[4];
                        ldm_x4(bq, bb + (uint32_t)(g * 16 * PADB + t * 32) + bRowOff);
                        if (act0) {
                            mma16816h(s[0][g * 2],     aH[0][t], bq[0], bq[1]);
                            mma16816h(s[0][g * 2 + 1], aH[0][t], bq[2], bq[3]);
                        }
                        mma16816h(s[1][g * 2],     aH[1][t], bq[0], bq[1]);
                        mma16816h(s[1][g * 2 + 1], aH[1][t], bq[2], bq[3]);
                    }
                }
            }

            uint32_t pa[2][4][4];
#pragma unroll
            for (int sub = 0; sub < 2; sub++) {
                if (sub == 0 && !act0) continue;
                const int r0 = wrow0 + sub * 16 + (lane >> 2);
                const int r1 = r0 + 8;

                if (j0 + 63 > wrow0 + sub * 16) {   // diagonal block: mask
                    const int cb = j0 + (lane & 3) * 2;
#pragma unroll
                    for (int g = 0; g < 8; g++) {
                        int c0 = cb + g * 8;
                        if (c0 > r0)     s[sub][g][0] = -1e30f;
                        if (c0 + 1 > r0) s[sub][g][1] = -1e30f;
                        if (c0 > r1)     s[sub][g][2] = -1e30f;
                        if (c0 + 1 > r1) s[sub][g][3] = -1e30f;
                    }
                }

                float mx0 = -1e30f, mx1 = -1e30f;
#pragma unroll
                for (int g = 0; g < 8; g++) {
                    mx0 = fmaxf(mx0, fmaxf(s[sub][g][0], s[sub][g][1]));
                    mx1 = fmaxf(mx1, fmaxf(s[sub][g][2], s[sub][g][3]));
                }
                mx0 = fmaxf(mx0, __shfl_xor_sync(0xffffffffu, mx0, 1));
                mx0 = fmaxf(mx0, __shfl_xor_sync(0xffffffffu, mx0, 2));
                mx1 = fmaxf(mx1, __shfl_xor_sync(0xffffffffu, mx1, 1));
                mx1 = fmaxf(mx1, __shfl_xor_sync(0xffffffffu, mx1, 2));

                const float mn0 = fmaxf(m_[sub][0], mx0);
                const float mn1 = fmaxf(m_[sub][1], mx1);
                const float cs0 = ex2f(m_[sub][0] - mn0);
                const float cs1 = ex2f(m_[sub][1] - mn1);
                m_[sub][0] = mn0; m_[sub][1] = mn1;
#pragma unroll
                for (int g = 0; g < 8; g++) {
                    o[sub][g][0] *= cs0; o[sub][g][1] *= cs0;
                    o[sub][g][2] *= cs1; o[sub][g][3] *= cs1;
                }
                lf[sub][0] *= cs0; lf[sub][1] *= cs0;
                lf[sub][2] *= cs1; lf[sub][3] *= cs1;

#pragma unroll
                for (int g = 0; g < 8; g++) {
                    uint32_t p01 = exp2_f16x2(s[sub][g][0] - mn0, s[sub][g][1] - mn0);
                    uint32_t p23 = exp2_f16x2(s[sub][g][2] - mn1, s[sub][g][3] - mn1);
                    if ((g & 1) == 0) { pa[sub][g >> 1][0] = p01; pa[sub][g >> 1][1] = p23; }
                    else              { pa[sub][g >> 1][2] = p01; pa[sub][g >> 1][3] = p23; }
                }
            }

            // O += P.V — V fragments shared across both slabs
            const uint32_t ONES = 0x3C003C00u;
#pragma unroll
            for (int t = 0; t < 4; t++) {
#pragma unroll
                for (int g = 0; g < 4; g++) {
                    uint32_t bv[4];
                    ldm_x4t(bv, vhb + (uint32_t)(t * 16 * PADB + g * 32) + vRowOff);
                    if (act0) {
                        mma16816h(o[0][g * 2],     pa[0][t], bv[0], bv[1]);
                        mma16816h(o[0][g * 2 + 1], pa[0][t], bv[2], bv[3]);
                    }
                    mma16816h(o[1][g * 2],     pa[1][t], bv[0], bv[1]);
                    mma16816h(o[1][g * 2 + 1], pa[1][t], bv[2], bv[3]);
                }
                if (act0) mma16816h(lf[0], pa[0][t], ONES, ONES);
                mma16816h(lf[1], pa[1][t], ONES, ONES);
            }
        }
        __syncthreads();
    }

    // Epilogue: write split [hi|hi|lo] bf16 layout straight into OS
    const int colb = h * DHEAD + (lane & 3) * 2;
#pragma unroll
    for (int sub = 0; sub < 2; sub++) {
        const float inv0 = 1.f / lf[sub][0], inv1 = 1.f / lf[sub][2];
        const int r0 = q0 + wid * 32 + sub * 16 + (lane >> 2);
#pragma unroll
        for (int g = 0; g < 8; g++) {
            int col = colb + g * 8;
            float a0 = o[sub][g][0] * inv0, a1 = o[sub][g][1] * inv0;
            float a2 = o[sub][g][2] * inv1, a3 = o[sub][g][3] * inv1;
            float h0 = __bfloat162float(__float2bfloat16(a0));
            float h1 = __bfloat162float(__float2bfloat16(a1));
            float h2 = __bfloat162float(__float2bfloat16(a2));
            float h3 = __bfloat162float(__float2bfloat16(a3));
            __nv_bfloat16* b0 = OS + (size_t)r0 * KP;
            __nv_bfloat16* b1 = OS + (size_t)(r0 + 8) * KP;
            store_bf16x2(b0 + col,            h0, h1);
            store_bf16x2(b0 + DIM + col,      h0, h1);
            store_bf16x2(b0 + 2 * DIM + col,  a0 - h0, a1 - h1);
            store_bf16x2(b1 + col,            h2, h3);
            store_bf16x2(b1 + DIM + col,      h2, h3);
            store_bf16x2(b1 + 2 * DIM + col,  a2 - h2, a3 - h3);
        }
    }
}

// ---------------------------------------------------------------------------
extern "C" void kernel_launch(void* const* d_in, const int* in_sizes, int n_in,
                              void* d_out, int out_size)
{
    const float* x  = (const float*)d_in[0];
    const float* Wq = (const float*)d_in[1];
    const float* Wk = (const float*)d_in[2];
    const float* Wv = (const float*)d_in[3];
    const float* Wo = (const float*)d_in[4];
    const float* bo = (const float*)d_in[5];
    float* out = (float*)d_out;

    __nv_bfloat16 *XS, *WTq, *WTk, *WTv, *WTo, *OS;
    __half *Qh, *Khi, *Klo, *Vh;
    cudaGetSymbolAddress((void**)&XS, g_XS);
    cudaGetSymbolAddress((void**)&WTq, g_WTq);
    cudaGetSymbolAddress((void**)&WTk, g_WTk);
    cudaGetSymbolAddress((void**)&WTv, g_WTv);
    cudaGetSymbolAddress((void**)&WTo, g_WTo);
    cudaGetSymbolAddress((void**)&OS, g_OS);
    cudaGetSymbolAddress((void**)&Qh, g_Qh);
    cudaGetSymbolAddress((void**)&Khi, g_Khi);
    cudaGetSymbolAddress((void**)&Klo, g_Klo);
    cudaGetSymbolAddress((void**)&Vh, g_Vh);

    cudaFuncSetAttribute(attn_mma_kernel,
                         cudaFuncAttributeMaxDynamicSharedMemorySize, ATT_SMEM);

    dim3 wgrid(DIM / 32, DIM / 32);
    split_w_kernel<<<wgrid, 256>>>(Wq, WTq, DIM, DIM);
    split_w_kernel<<<wgrid, 256>>>(Wk, WTk, DIM, DIM);
    split_w_kernel<<<wgrid, 256>>>(Wv, WTv, DIM, DIM);
    split_w_kernel<<<wgrid, 256>>>(Wo, WTo, DIM, DIM);

    split_a_kernel<<<(SEQ * DIM) / (256 * 4), 256>>>(x, XS, DIM);

    dim3 ggrid(DIM / 128, SEQ / 128);
    gemm_mma_kernel<0><<<ggrid, 128>>>(XS, WTq, nullptr, nullptr, Qh, nullptr, DIM);
    gemm_mma_kernel<1><<<ggrid, 128>>>(XS, WTk, nullptr, nullptr, Khi, Klo, DIM);
    gemm_mma_kernel<2><<<ggrid, 128>>>(XS, WTv, nullptr, nullptr, Vh, nullptr, DIM);

    dim3 agrid(SEQ / QROWS, HEADS);
    attn_mma_kernel<<<agrid, 256, ATT_SMEM>>>(Qh, Khi, Klo, Vh, OS);

    gemm_mma_kernel<3><<<ggrid, 128>>>(OS, WTo, bo, out, nullptr, nullptr, DIM);
}